// round 16
// baseline (speedup 1.0000x reference)
#include <cuda_runtime.h>
#include <cuda_bf16.h>
#include <cstdint>

#define B_  4
#define S_  1024
#define E_  768
#define H_  12
#define HD_ 64
#define BH_ (B_ * H_)

#define XN_ (4096 * 768)
#define WN_ (768 * 768)
#define QKV_N (BH_ * S_ * HD_)
#define MB_WORDS (B_ * S_ * (S_ / 32))

// ---------------------------------------------------------------------------
// Scratch (device globals; no allocations allowed)
// ---------------------------------------------------------------------------
__device__ __nv_bfloat16 g_Xhi[3 * XN_];   // slot 0 reused for attn-out before O-proj
__device__ __nv_bfloat16 g_Xlo[3 * XN_];
__device__ __nv_bfloat16 g_WhiA[4 * WN_];
__device__ __nv_bfloat16 g_WloA[4 * WN_];

__device__ __nv_bfloat16 g_Qhi[QKV_N], g_Qlo[QKV_N];    // [B,H,S,HD]
__device__ __nv_bfloat16 g_Khi[QKV_N], g_Klo[QKV_N];    // [B,H,S,HD]
__device__ __nv_bfloat16 g_Vthi[QKV_N], g_Vtlo[QKV_N];  // [B,H,HD,S]

__device__ uint32_t g_mbits[MB_WORDS];                  // packed mask bits

// ---------------------------------------------------------------------------
// helpers (arch-portable PTX; no tcgen05 — harness compiles compute_103)
// ---------------------------------------------------------------------------
__device__ __forceinline__ uint32_t smem_u32(const void* p) {
    uint32_t a;
    asm("{ .reg .u64 t; cvta.to.shared.u64 t, %1; cvt.u32.u64 %0, t; }"
        : "=r"(a) : "l"(p));
    return a;
}

__device__ __forceinline__ void mma_bf16(float* d, const uint32_t* a,
                                         uint32_t b0, uint32_t b1) {
    asm volatile(
        "mma.sync.aligned.m16n8k16.row.col.f32.bf16.bf16.f32 "
        "{%0,%1,%2,%3}, {%4,%5,%6,%7}, {%8,%9}, {%0,%1,%2,%3};"
        : "+f"(d[0]), "+f"(d[1]), "+f"(d[2]), "+f"(d[3])
        : "r"(a[0]), "r"(a[1]), "r"(a[2]), "r"(a[3]),
          "r"(b0), "r"(b1));
}

__device__ __forceinline__ void ldmx4(uint32_t* r, uint32_t addr) {
    asm volatile("ldmatrix.sync.aligned.m8n8.x4.shared.b16 {%0,%1,%2,%3}, [%4];"
        : "=r"(r[0]), "=r"(r[1]), "=r"(r[2]), "=r"(r[3]) : "r"(addr));
}

__device__ __forceinline__ void cp_async16(uint32_t saddr, const void* gptr) {
    asm volatile("cp.async.cg.shared.global [%0], [%1], 16;"
                 :: "r"(saddr), "l"(gptr));
}
__device__ __forceinline__ void cp_commit() {
    asm volatile("cp.async.commit_group;");
}
template <int N>
__device__ __forceinline__ void cp_wait() {
    asm volatile("cp.async.wait_group %0;" :: "n"(N));
}

__device__ __forceinline__ float ex2(float x) {
    float y;
    asm("ex2.approx.ftz.f32 %0, %1;" : "=f"(y) : "f"(x));
    return y;
}

__device__ __forceinline__ uint32_t pack_bf16(float x, float y) {
    __nv_bfloat162 t = __floats2bfloat162_rn(x, y);
    return *(uint32_t*)&t;
}
__device__ __forceinline__ void split_bf16(float x, __nv_bfloat16& hi,
                                           __nv_bfloat16& lo) {
    hi = __float2bfloat16_rn(x);
    lo = __float2bfloat16_rn(x - __bfloat162float(hi));
}
__device__ __forceinline__ uint32_t pack2h(__nv_bfloat16 a, __nv_bfloat16 b) {
    return (uint32_t)*(uint16_t*)&a | ((uint32_t)*(uint16_t*)&b << 16);
}

// ---------------------------------------------------------------------------
// Prepass: fp32 -> bf16 hi/lo split. blockIdx.y selects source tensor.
// ---------------------------------------------------------------------------
__global__ __launch_bounds__(256) void convert_split(
    const float* __restrict__ s0, const float* __restrict__ s1,
    const float* __restrict__ s2, const float* __restrict__ s3,
    __nv_bfloat16* __restrict__ hi, __nv_bfloat16* __restrict__ lo, int n)
{
    const float* s = (blockIdx.y == 0) ? s0 : (blockIdx.y == 1) ? s1
                   : (blockIdx.y == 2) ? s2 : s3;
    size_t off = (size_t)blockIdx.y * n;
    int i = (blockIdx.x * 256 + threadIdx.x) * 4;
    float4 v = *(const float4*)&s[i];
    __nv_bfloat162 h01 = __floats2bfloat162_rn(v.x, v.y);
    __nv_bfloat162 h23 = __floats2bfloat162_rn(v.z, v.w);
    __nv_bfloat162 l01 = __floats2bfloat162_rn(v.x - __bfloat162float(h01.x),
                                               v.y - __bfloat162float(h01.y));
    __nv_bfloat162 l23 = __floats2bfloat162_rn(v.z - __bfloat162float(h23.x),
                                               v.w - __bfloat162float(h23.y));
    uint2 hv = { *(uint32_t*)&h01, *(uint32_t*)&h23 };
    uint2 lv = { *(uint32_t*)&l01, *(uint32_t*)&l23 };
    *(uint2*)&hi[off + i] = hv;
    *(uint2*)&lo[off + i] = lv;
}

// ---------------------------------------------------------------------------
// Prepass: pack mask int32 0/1 -> bitmask (1 word per 32 cols).
// ---------------------------------------------------------------------------
__global__ __launch_bounds__(256) void mask_pack(const int* __restrict__ mask,
                                                 uint32_t* __restrict__ bits)
{
    int w = blockIdx.x * 256 + threadIdx.x;
    const int* src = mask + (size_t)w * 32;
    uint32_t v = 0;
    #pragma unroll
    for (int i = 0; i < 8; ++i) {
        int4 m4 = *(const int4*)&src[i * 4];
        v |= (uint32_t)(m4.x & 1) << (4 * i + 0);
        v |= (uint32_t)(m4.y & 1) << (4 * i + 1);
        v |= (uint32_t)(m4.z & 1) << (4 * i + 2);
        v |= (uint32_t)(m4.w & 1) << (4 * i + 3);
    }
    bits[w] = v;
}

// ---------------------------------------------------------------------------
// bf16-split GEMM v5: R13 config (128x128, 512 thr, 3-stage ring, one barrier
// per K-tile) + ALL 16 fragment ldmatrix hoisted above the 96-MMA burst so
// the LSU pipelines the loads and the tensor pipe gets an uninterrupted run.
// ---------------------------------------------------------------------------
#define GM 128
#define GN 128
#define RW 20
#define STW (4 * 128 * RW)                       // words per stage (40KB)
#define G3_SMEM_BYTES (3 * STW * 4)              // 120KB, 3 stages

__global__ __launch_bounds__(512, 1) void gemm_bf16(
    const __nv_bfloat16* __restrict__ XhiB, const __nv_bfloat16* __restrict__ XloB,
    const __nv_bfloat16* __restrict__ WhiB, const __nv_bfloat16* __restrict__ WloB,
    const float* __restrict__ bias0, const float* __restrict__ bias1,
    const float* __restrict__ bias2,
    float* __restrict__ out0, int layout)
{
    extern __shared__ uint32_t sm3[];

    const int z = blockIdx.z;
    const __nv_bfloat16* Ahi = XhiB + (size_t)z * XN_;
    const __nv_bfloat16* Alo = XloB + (size_t)z * XN_;
    const __nv_bfloat16* Whi = WhiB + (size_t)z * WN_;
    const __nv_bfloat16* Wlo = WloB + (size_t)z * WN_;
    const float* bias = (z == 0) ? bias0 : (z == 1) ? bias1 : bias2;

    const int tid  = threadIdx.x;
    const int wid  = tid >> 5;
    const int lane = tid & 31;
    const int wm   = wid >> 2;
    const int wn   = wid & 3;
    const int gid  = lane >> 2;
    const int tig  = lane & 3;
    const int row0 = blockIdx.x * GM;
    const int col0 = blockIdx.y * GN;

    const int sr = tid >> 2;
    const int sq = tid & 3;
    const uint32_t base = smem_u32(sm3);
    const uint32_t stByte = (sr * RW + sq * 4) * 4;

    const __nv_bfloat16* gA0 = Ahi + (size_t)(row0 + sr) * E_ + sq * 8;
    const __nv_bfloat16* gA1 = Alo + (size_t)(row0 + sr) * E_ + sq * 8;
    const __nv_bfloat16* gB0 = Whi + (size_t)(col0 + sr) * E_ + sq * 8;
    const __nv_bfloat16* gB1 = Wlo + (size_t)(col0 + sr) * E_ + sq * 8;

    const uint32_t SUB = 128 * RW * 4;
    const uint32_t STAGE = STW * 4;

    const uint32_t aOff = ((32 * wm + (lane & 15)) * RW + (lane >> 4) * 4) * 4;
    const uint32_t g    = lane >> 3;
    const uint32_t bOff = ((32 * wn + (g >> 1) * 8 + (lane & 7)) * RW + (g & 1) * 4) * 4;

    float acc[2][4][4];
    #pragma unroll
    for (int mt = 0; mt < 2; ++mt)
        #pragma unroll
        for (int nt = 0; nt < 4; ++nt)
            #pragma unroll
            for (int j = 0; j < 4; ++j) acc[mt][nt][j] = 0.f;

    // prologue: stages 0 and 1 in flight
    #pragma unroll
    for (int p = 0; p < 2; ++p) {
        uint32_t d = base + p * STAGE + stByte;
        int go = p * 32;
        cp_async16(d + 0 * SUB, gA0 + go);
        cp_async16(d + 1 * SUB, gA1 + go);
        cp_async16(d + 2 * SUB, gB0 + go);
        cp_async16(d + 3 * SUB, gB1 + go);
        cp_commit();
    }

    const int NKT = E_ / 32;                     // 24
    int stg_idx = 0;
    for (int kt = 0; kt < NKT; ++kt) {
        cp_wait<1>();                            // stage kt resident
        __syncthreads();                         // also proves compute kt-1 done

        if (kt + 2 < NKT) {                      // prefetch kt+2 into (kt+2)%3
            int pst = stg_idx + 2; if (pst >= 3) pst -= 3;
            uint32_t d = base + pst * STAGE + stByte;
            int go = (kt + 2) * 32;
            cp_async16(d + 0 * SUB, gA0 + go);
            cp_async16(d + 1 * SUB, gA1 + go);
            cp_async16(d + 2 * SUB, gB0 + go);
            cp_async16(d + 3 * SUB, gB1 + go);
        }
        cp_commit();

        const uint32_t stg = base + stg_idx * STAGE;
        const uint32_t aHiB = stg;
        const uint32_t aLoB = stg + SUB;
        const uint32_t bHiB = stg + 2 * SUB;
        const uint32_t bLoB = stg + 3 * SUB;

        // ---- hoisted fragment loads: all 16 ldmatrix issued back-to-back
        uint32_t ah[2][2][4], al[2][2][4], bh[2][2][4], bl[2][2][4];
        #pragma unroll
        for (int ks = 0; ks < 2; ++ks) {
            #pragma unroll
            for (int mt = 0; mt < 2; ++mt) {
                ldmx4(ah[ks][mt], aHiB + aOff + mt * (16 * RW * 4) + ks * 32);
                ldmx4(al[ks][mt], aLoB + aOff + mt * (16 * RW * 4) + ks * 32);
            }
            #pragma unroll
            for (int p = 0; p < 2; ++p) {
                ldmx4(bh[ks][p], bHiB + bOff + p * (16 * RW * 4) + ks * 32);
                ldmx4(bl[ks][p], bLoB + bOff + p * (16 * RW * 4) + ks * 32);
            }
        }

        // ---- 96-MMA burst
        #pragma unroll
        for (int ks = 0; ks < 2; ++ks)
            #pragma unroll
            for (int mt = 0; mt < 2; ++mt)
                #pragma unroll
                for (int nt = 0; nt < 4; ++nt) {
                    const int p = nt >> 1, j = (nt & 1) * 2;
                    mma_bf16(acc[mt][nt], ah[ks][mt], bh[ks][p][j], bh[ks][p][j + 1]);
                    mma_bf16(acc[mt][nt], ah[ks][mt], bl[ks][p][j], bl[ks][p][j + 1]);
                    mma_bf16(acc[mt][nt], al[ks][mt], bh[ks][p][j], bh[ks][p][j + 1]);
                }

        if (++stg_idx == 3) stg_idx = 0;
    }

    // ---- Epilogue
    #pragma unroll
    for (int mt = 0; mt < 2; ++mt) {
        #pragma unroll
        for (int nt = 0; nt < 4; ++nt) {
            int cc = col0 + 32 * wn + 8 * nt + 2 * tig;
            float b0 = bias[cc], b1 = bias[cc + 1];
            #pragma unroll
            for (int half = 0; half < 2; ++half) {
                int rr = row0 + 32 * wm + 16 * mt + gid + 8 * half;
                float ox = acc[mt][nt][2 * half + 0] + b0;
                float oy = acc[mt][nt][2 * half + 1] + b1;
                if (layout == 0) {
                    float2 o = { ox, oy };
                    *(float2*)&out0[(size_t)rr * E_ + cc] = o;
                } else {
                    int b  = rr >> 10;
                    int s  = rr & (S_ - 1);
                    int hh = cc >> 6;
                    int hd = cc & 63;
                    __nv_bfloat16 hx, lx, hy, ly;
                    split_bf16(ox, hx, lx);
                    split_bf16(oy, hy, ly);
                    if (z <= 1) {
                        __nv_bfloat16* Dhi = (z == 0) ? g_Qhi : g_Khi;
                        __nv_bfloat16* Dlo = (z == 0) ? g_Qlo : g_Klo;
                        size_t idx = ((size_t)(b * H_ + hh) * S_ + s) * HD_ + hd;
                        *(uint32_t*)&Dhi[idx] = pack2h(hx, hy);
                        *(uint32_t*)&Dlo[idx] = pack2h(lx, ly);
                    } else {
                        size_t idx = ((size_t)(b * H_ + hh) * HD_ + hd) * S_ + s;
                        g_Vthi[idx]      = hx;
                        g_Vthi[idx + S_] = hy;
                        g_Vtlo[idx]      = lx;
                        g_Vtlo[idx + S_] = ly;
                    }
                }
            }
        }
    }
}

// ---------------------------------------------------------------------------
// Flash attention (unchanged from R12): pre-split bf16 operands, cp.async
// double-buffered KV, ldmatrix fragment loads, 2 CTAs/SM, max-free softmax,
// bitmask masking, deferred l-reduction.
// ---------------------------------------------------------------------------
#define ATK 64
#define AQ  128
#define AW  36
#define QW  (AQ * AW)
#define KVB (ATK * AW)
#define KVSTAGE (4 * KVB)
#define ASM_WORDS (2 * QW + 2 * KVSTAGE)
#define ASM_BYTES (ASM_WORDS * 4)     // 110592 B -> 2 CTAs = 216KB

__global__ __launch_bounds__(256, 2) void attn_mma(
    const __nv_bfloat16* __restrict__ Qhi, const __nv_bfloat16* __restrict__ Qlo,
    const __nv_bfloat16* __restrict__ Khi, const __nv_bfloat16* __restrict__ Klo,
    const __nv_bfloat16* __restrict__ Vthi, const __nv_bfloat16* __restrict__ Vtlo,
    const uint32_t* __restrict__ mbits,
    __nv_bfloat16* __restrict__ xhi, __nv_bfloat16* __restrict__ xlo)
{
    extern __shared__ uint32_t asm_[];
    uint32_t* sQhi = asm_;
    uint32_t* sQlo = sQhi + QW;

    const int tid  = threadIdx.x;
    const int wid  = tid >> 5;
    const int lane = tid & 31;
    const int gid  = lane >> 2;
    const int tig  = lane & 3;
    const int qt   = blockIdx.x;
    const int bh   = blockIdx.y;
    const int b    = bh / H_;
    const int h    = bh % H_;
    const int q0   = qt * AQ;

    const uint32_t base = smem_u32(asm_);
    const float CEXP = 0.18033688011112042f;     // 0.125 * log2(e)

    const __nv_bfloat16* Qh = Qhi + (size_t)bh * S_ * HD_;
    const __nv_bfloat16* Ql = Qlo + (size_t)bh * S_ * HD_;
    const __nv_bfloat16* Kh = Khi + (size_t)bh * S_ * HD_;
    const __nv_bfloat16* Kl = Klo + (size_t)bh * S_ * HD_;
    const __nv_bfloat16* Vh = Vthi + (size_t)bh * HD_ * S_;
    const __nv_bfloat16* Vl = Vtlo + (size_t)bh * HD_ * S_;

    // ---- stage Q (both buffers) + KV tile 0
    #pragma unroll
    for (int i = 0; i < 8; ++i) {
        int c = tid + i * 256;
        int buf = c >> 10;
        int rem = c & 1023;
        int r = rem >> 3, c16 = rem & 7;
        const __nv_bfloat16* src = (buf ? Ql : Qh) + (size_t)(q0 + r) * HD_ + c16 * 8;
        cp_async16(base + buf * (QW * 4) + r * 144 + c16 * 16, src);
    }
    #pragma unroll
    for (int i = 0; i < 8; ++i) {
        int c = tid + i * 256;
        int buf = c >> 9;
        int rem = c & 511;
        int r = rem >> 3, c16 = rem & 7;
        const __nv_bfloat16* src =
            (buf == 0) ? Kh + (size_t)r * HD_ + c16 * 8 :
            (buf == 1) ? Kl + (size_t)r * HD_ + c16 * 8 :
            (buf == 2) ? Vh + (size_t)r * S_ + c16 * 8 :
                         Vl + (size_t)r * S_ + c16 * 8;
        cp_async16(base + (2 * QW + buf * KVB) * 4 + r * 144 + c16 * 16, src);
    }
    cp_commit();
    cp_wait<0>();
    __syncthreads();

    // ---- per-warp Q fragments (persistent)
    uint32_t qh[4][4], ql[4][4];
    {
        const int r0 = wid * 16;
        #pragma unroll
        for (int ks = 0; ks < 4; ++ks) {
            int bidx = (r0 + gid) * AW + 8 * ks + tig;
            qh[ks][0] = sQhi[bidx];
            qh[ks][1] = sQhi[bidx + 8 * AW];
            qh[ks][2] = sQhi[bidx + 4];
            qh[ks][3] = sQhi[bidx + 8 * AW + 4];
            ql[ks][0] = sQlo[bidx];
            ql[ks][1] = sQlo[bidx + 8 * AW];
            ql[ks][2] = sQlo[bidx + 4];
            ql[ks][3] = sQlo[bidx + 8 * AW + 4];
        }
    }

    float Oa[8][4];
    #pragma unroll
    for (int t = 0; t < 8; ++t)
        #pragma unroll
        for (int j = 0; j < 4; ++j) Oa[t][j] = 0.f;
    float l0 = 0.f, l1 = 0.f;

    const int qr0 = q0 + wid * 16 + gid;
    const uint32_t* mb0 = mbits + ((size_t)b * S_ + qr0) * (S_ / 32);
    const uint32_t* mb1 = mb0 + 8 * (S_ / 32);

    const uint32_t g = lane >> 3;
    const uint32_t fOff = (((g >> 1) * 8 + (lane & 7)) * AW + (g & 1) * 4) * 4;

    const int NT = S_ / ATK;                     // 16
    for (int jt = 0; jt < NT; ++jt) {
        if (jt + 1 < NT) {
            int nst = (jt + 1) & 1;
            int ko = (jt + 1) * ATK;
            #pragma unroll
            for (int i = 0; i < 8; ++i) {
                int c = tid + i * 256;
                int buf = c >> 9;
                int rem = c & 511;
                int r = rem >> 3, c16 = rem & 7;
                const __nv_bfloat16* src =
                    (buf == 0) ? Kh + (size_t)(ko + r) * HD_ + c16 * 8 :
                    (buf == 1) ? Kl + (size_t)(ko + r) * HD_ + c16 * 8 :
                    (buf == 2) ? Vh + (size_t)r * S_ + ko + c16 * 8 :
                                 Vl + (size_t)r * S_ + ko + c16 * 8;
                cp_async16(base + (2 * QW + nst * KVSTAGE + buf * KVB) * 4
                           + r * 144 + c16 * 16, src);
            }
            cp_commit();
            cp_wait<1>();
        } else {
            cp_wait<0>();
        }
        uint2 mw0 = *(const uint2*)&mb0[2 * jt];
        uint2 mw1 = *(const uint2*)&mb1[2 * jt];
        __syncthreads();

        const uint32_t kvByte = base + (2 * QW + (jt & 1) * KVSTAGE) * 4;
        const uint32_t kHiB = kvByte;
        const uint32_t kLoB = kvByte + KVB * 4;
        const uint32_t vHiB = kvByte + 2 * KVB * 4;
        const uint32_t vLoB = kvByte + 3 * KVB * 4;

        // ---- S = Q K^T
        float sa[8][4];
        #pragma unroll
        for (int t = 0; t < 8; ++t)
            #pragma unroll
            for (int j = 0; j < 4; ++j) sa[t][j] = 0.f;

        #pragma unroll
        for (int ks = 0; ks < 4; ++ks) {
            #pragma unroll
            for (int tt = 0; tt < 4; ++tt) {
                uint32_t kh4[4], kl4[4];
                uint32_t a = fOff + (16 * tt * AW + 8 * ks) * 4;
                ldmx4(kh4, kHiB + a);
                ldmx4(kl4, kLoB + a);
                mma_bf16(sa[2 * tt],     qh[ks], kh4[0], kh4[1]);
                mma_bf16(sa[2 * tt],     qh[ks], kl4[0], kl4[1]);
                mma_bf16(sa[2 * tt],     ql[ks], kh4[0], kh4[1]);
                mma_bf16(sa[2 * tt + 1], qh[ks], kh4[2], kh4[3]);
                mma_bf16(sa[2 * tt + 1], qh[ks], kl4[2], kl4[3]);
                mma_bf16(sa[2 * tt + 1], ql[ks], kh4[2], kh4[3]);
            }
        }

        // ---- masked exp (max-free)
        #pragma unroll
        for (int t = 0; t < 8; ++t) {
            int bit = 8 * (t & 3) + 2 * tig;
            uint32_t w0 = (t < 4) ? mw0.x : mw0.y;
            uint32_t w1 = (t < 4) ? mw1.x : mw1.y;
            float p0 = ((w0 >> bit) & 1)       ? ex2(sa[t][0] * CEXP) : 0.f;
            float p1 = ((w0 >> (bit + 1)) & 1) ? ex2(sa[t][1] * CEXP) : 0.f;
            float p2 = ((w1 >> bit) & 1)       ? ex2(sa[t][2] * CEXP) : 0.f;
            float p3 = ((w1 >> (bit + 1)) & 1) ? ex2(sa[t][3] * CEXP) : 0.f;
            sa[t][0] = p0; sa[t][1] = p1; sa[t][2] = p2; sa[t][3] = p3;
            l0 += p0 + p1; l1 += p2 + p3;
        }

        // ---- O += P V
        #pragma unroll
        for (int ks = 0; ks < 4; ++ks) {
            const int t0 = 2 * ks, t1 = 2 * ks + 1;
            uint32_t ah[4], al[4];
            ah[0] = pack_bf16(sa[t0][0], sa[t0][1]);
            ah[1] = pack_bf16(sa[t0][2], sa[t0][3]);
            ah[2] = pack_bf16(sa[t1][0], sa[t1][1]);
            ah[3] = pack_bf16(sa[t1][2], sa[t1][3]);
            {
                __nv_bfloat162 h0 = *(__nv_bfloat162*)&ah[0];
                __nv_bfloat162 h1 = *(__nv_bfloat162*)&ah[1];
                __nv_bfloat162 h2 = *(__nv_bfloat162*)&ah[2];
                __nv_bfloat162 h3 = *(__nv_bfloat162*)&ah[3];
                al[0] = pack_bf16(sa[t0][0] - __bfloat162float(h0.x),
                                  sa[t0][1] - __bfloat162float(h0.y));
                al[1] = pack_bf16(sa[t0][2] - __bfloat162float(h1.x),
                                  sa[t0][3] - __bfloat162float(h1.y));
                al[2] = pack_bf16(sa[t1][0] - __bfloat162float(h2.x),
                                  sa[t1][1] - __bfloat162float(h2.y));
                al[3] = pack_bf16(sa[t1][2] - __bfloat162float(h3.x),
                                  sa[t1][3] - __bfloat162float(h3.y));
            }
            #pragma unroll
            for (int nn = 0; nn < 4; ++nn) {
                uint32_t vh4[4], vl4[4];
                uint32_t a = fOff + (16 * nn * AW + 8 * ks) * 4;
                ldmx4(vh4, vHiB + a);
                ldmx4(vl4, vLoB + a);
                mma_bf16(Oa[2 * nn],     ah, vh4[0], vh4[1]);
                mma_bf16(Oa[2 * nn],     ah, vl4[0], vl4[1]);
                mma_bf16(Oa[2 * nn],     al, vh4[0], vh4[1]);
                mma_bf16(Oa[2 * nn + 1], ah, vh4[2], vh4[3]);
                mma_bf16(Oa[2 * nn + 1], ah, vl4[2], vl4[3]);
                mma_bf16(Oa[2 * nn + 1], al, vh4[2], vh4[3]);
            }
        }
        __syncthreads();
    }

    // ---- single deferred l-reduction
    #pragma unroll
    for (int off = 1; off <= 2; off <<= 1) {
        l0 += __shfl_xor_sync(0xffffffffu, l0, off);
        l1 += __shfl_xor_sync(0xffffffffu, l1, off);
    }

    // ---- epilogue: write pre-split bf16 into O-proj A operand
    float inv0 = (l0 > 0.f) ? 1.f / l0 : 0.f;
    float inv1 = (l1 > 0.f) ? 1.f / l1 : 0.f;
    size_t x0 = ((size_t)b * S_ + qr0) * E_ + h * HD_;
    size_t x1 = x0 + 8 * (size_t)E_;
    #pragma unroll
    for (int t = 0; t < 8; ++t) {
        float a0 = Oa[t][0] * inv0, a1 = Oa[t][1] * inv0;
        float b0 = Oa[t][2] * inv1, b1 = Oa[t][3] * inv1;
        __nv_bfloat16 hx, lx, hy, ly;
        split_bf16(a0, hx, lx); split_bf16(a1, hy, ly);
        *(uint32_t*)&xhi[x0 + 8 * t + 2 * tig] = pack2h(hx, hy);
        *(uint32_t*)&xlo[x0 + 8 * t + 2 * tig] = pack2h(lx, ly);
        split_bf16(b0, hx, lx); split_bf16(b1, hy, ly);
        *(uint32_t*)&xhi[x1 + 8 * t + 2 * tig] = pack2h(hx, hy);
        *(uint32_t*)&xlo[x1 + 8 * t + 2 * tig] = pack2h(lx, ly);
    }
}

// ---------------------------------------------------------------------------
// Launch
// ---------------------------------------------------------------------------
extern "C" void kernel_launch(void* const* d_in, const int* in_sizes, int n_in,
                              void* d_out, int out_size)
{
    const float* query = (const float*)d_in[0];
    const float* key_  = (const float*)d_in[1];
    const float* value = (const float*)d_in[2];
    const int*   mask  = (const int*)d_in[3];
    const float* Wq = (const float*)d_in[4];  const float* bq = (const float*)d_in[5];
    const float* Wk = (const float*)d_in[6];  const float* bk = (const float*)d_in[7];
    const float* Wv = (const float*)d_in[8];  const float* bv = (const float*)d_in[9];
    const float* Wo = (const float*)d_in[10]; const float* bo = (const float*)d_in[11];

    __nv_bfloat16 *xhi, *xlo, *whi, *wlo;
    cudaGetSymbolAddress((void**)&xhi, g_Xhi);
    cudaGetSymbolAddress((void**)&xlo, g_Xlo);
    cudaGetSymbolAddress((void**)&whi, g_WhiA);
    cudaGetSymbolAddress((void**)&wlo, g_WloA);

    __nv_bfloat16 *qhi, *qlo, *khi, *klo, *vthi, *vtlo;
    cudaGetSymbolAddress((void**)&qhi,  g_Qhi);
    cudaGetSymbolAddress((void**)&qlo,  g_Qlo);
    cudaGetSymbolAddress((void**)&khi,  g_Khi);
    cudaGetSymbolAddress((void**)&klo,  g_Klo);
    cudaGetSymbolAddress((void**)&vthi, g_Vthi);
    cudaGetSymbolAddress((void**)&vtlo, g_Vtlo);

    uint32_t* mbits;
    cudaGetSymbolAddress((void**)&mbits, g_mbits);

    cudaFuncSetAttribute(gemm_bf16, cudaFuncAttributeMaxDynamicSharedMemorySize,
                         G3_SMEM_BYTES);
    cudaFuncSetAttribute(attn_mma, cudaFuncAttributeMaxDynamicSharedMemorySize,
                         ASM_BYTES);

    // prepasses
    convert_split<<<dim3(XN_ / 1024, 3), 256>>>(query, key_, value, query,
                                                xhi, xlo, XN_);
    convert_split<<<dim3(WN_ / 1024, 4), 256>>>(Wq, Wk, Wv, Wo,
                                                whi, wlo, WN_);
    mask_pack<<<MB_WORDS / 256, 256>>>(mask, mbits);

    // fused QKV projection -> pre-split bf16 Q/K/Vt
    gemm_bf16<<<dim3(B_ * S_ / GM, E_ / GN, 3), 512, G3_SMEM_BYTES>>>(
        xhi, xlo, whi, wlo, bq, bk, bv, nullptr, 1);

    // attention -> writes split bf16 directly into X slot 0
    attn_mma<<<dim3(S_ / AQ, BH_), 256, ASM_BYTES>>>(
        qhi, qlo, khi, klo, vthi, vtlo, mbits, xhi, xlo);

    // O-projection (reads X slot 0, W slot 3)
    gemm_bf16<<<dim3(B_ * S_ / GM, E_ / GN, 1), 512, G3_SMEM_BYTES>>>(
        xhi, xlo, whi + 3 * (size_t)WN_, wlo + 3 * (size_t)WN_,
        bo, bo, bo, (float*)d_out, 0);
}

// round 17
// speedup vs baseline: 1.0247x; 1.0247x over previous
#include <cuda_runtime.h>
#include <cuda_bf16.h>
#include <cstdint>

#define B_  4
#define S_  1024
#define E_  768
#define H_  12
#define HD_ 64
#define BH_ (B_ * H_)

#define XN_ (4096 * 768)
#define WN_ (768 * 768)
#define QKV_N (BH_ * S_ * HD_)
#define MB_WORDS (B_ * S_ * (S_ / 32))

// fused prepass block ranges (256 threads each)
#define XBLK (XN_ / 1024)              // 3072 blocks per X tensor
#define WBLK (WN_ / 1024)              // 576 blocks per W tensor
#define PRE_X (3 * XBLK)               // 9216
#define PRE_W (4 * WBLK)               // 2304
#define PRE_M (MB_WORDS / 256)         // 512
#define PRE_TOTAL (PRE_X + PRE_W + PRE_M)

// ---------------------------------------------------------------------------
// Scratch (device globals; no allocations allowed)
// ---------------------------------------------------------------------------
__device__ __nv_bfloat16 g_Xhi[3 * XN_];   // slot 0 reused for attn-out before O-proj
__device__ __nv_bfloat16 g_Xlo[3 * XN_];
__device__ __nv_bfloat16 g_WhiA[4 * WN_];
__device__ __nv_bfloat16 g_WloA[4 * WN_];

__device__ __nv_bfloat16 g_Qhi[QKV_N], g_Qlo[QKV_N];    // [B,H,S,HD]
__device__ __nv_bfloat16 g_Khi[QKV_N], g_Klo[QKV_N];    // [B,H,S,HD]
__device__ __nv_bfloat16 g_Vthi[QKV_N], g_Vtlo[QKV_N];  // [B,H,HD,S]

__device__ uint32_t g_mbits[MB_WORDS];                  // packed mask bits

// ---------------------------------------------------------------------------
// helpers (arch-portable PTX; no tcgen05 — harness compiles compute_103)
// ---------------------------------------------------------------------------
__device__ __forceinline__ uint32_t smem_u32(const void* p) {
    uint32_t a;
    asm("{ .reg .u64 t; cvta.to.shared.u64 t, %1; cvt.u32.u64 %0, t; }"
        : "=r"(a) : "l"(p));
    return a;
}

__device__ __forceinline__ void mma_bf16(float* d, const uint32_t* a,
                                         uint32_t b0, uint32_t b1) {
    asm volatile(
        "mma.sync.aligned.m16n8k16.row.col.f32.bf16.bf16.f32 "
        "{%0,%1,%2,%3}, {%4,%5,%6,%7}, {%8,%9}, {%0,%1,%2,%3};"
        : "+f"(d[0]), "+f"(d[1]), "+f"(d[2]), "+f"(d[3])
        : "r"(a[0]), "r"(a[1]), "r"(a[2]), "r"(a[3]),
          "r"(b0), "r"(b1));
}

__device__ __forceinline__ void ldmx4(uint32_t* r, uint32_t addr) {
    asm volatile("ldmatrix.sync.aligned.m8n8.x4.shared.b16 {%0,%1,%2,%3}, [%4];"
        : "=r"(r[0]), "=r"(r[1]), "=r"(r[2]), "=r"(r[3]) : "r"(addr));
}

__device__ __forceinline__ void cp_async16(uint32_t saddr, const void* gptr) {
    asm volatile("cp.async.cg.shared.global [%0], [%1], 16;"
                 :: "r"(saddr), "l"(gptr));
}
__device__ __forceinline__ void cp_commit() {
    asm volatile("cp.async.commit_group;");
}
template <int N>
__device__ __forceinline__ void cp_wait() {
    asm volatile("cp.async.wait_group %0;" :: "n"(N));
}

__device__ __forceinline__ float ex2(float x) {
    float y;
    asm("ex2.approx.ftz.f32 %0, %1;" : "=f"(y) : "f"(x));
    return y;
}

__device__ __forceinline__ uint32_t pack_bf16(float x, float y) {
    __nv_bfloat162 t = __floats2bfloat162_rn(x, y);
    return *(uint32_t*)&t;
}
__device__ __forceinline__ void split_bf16(float x, __nv_bfloat16& hi,
                                           __nv_bfloat16& lo) {
    hi = __float2bfloat16_rn(x);
    lo = __float2bfloat16_rn(x - __bfloat162float(hi));
}
__device__ __forceinline__ uint32_t pack2h(__nv_bfloat16 a, __nv_bfloat16 b) {
    return (uint32_t)*(uint16_t*)&a | ((uint32_t)*(uint16_t*)&b << 16);
}

// ---------------------------------------------------------------------------
// Fused prepass: one launch covers X-convert (3 tensors), W-convert (4
// tensors), and mask bit-pack, dispatched on flat blockIdx.x.
// ---------------------------------------------------------------------------
__device__ __forceinline__ void do_convert4(const float* __restrict__ s,
                                            __nv_bfloat16* __restrict__ hi,
                                            __nv_bfloat16* __restrict__ lo,
                                            size_t elem0)
{
    float4 v = *(const float4*)&s[elem0];
    __nv_bfloat162 h01 = __floats2bfloat162_rn(v.x, v.y);
    __nv_bfloat162 h23 = __floats2bfloat162_rn(v.z, v.w);
    __nv_bfloat162 l01 = __floats2bfloat162_rn(v.x - __bfloat162float(h01.x),
                                               v.y - __bfloat162float(h01.y));
    __nv_bfloat162 l23 = __floats2bfloat162_rn(v.z - __bfloat162float(h23.x),
                                               v.w - __bfloat162float(h23.y));
    uint2 hv = { *(uint32_t*)&h01, *(uint32_t*)&h23 };
    uint2 lv = { *(uint32_t*)&l01, *(uint32_t*)&l23 };
    *(uint2*)&hi[elem0] = hv;
    *(uint2*)&lo[elem0] = lv;
}

__global__ __launch_bounds__(256) void prepass_fused(
    const float* __restrict__ q, const float* __restrict__ k,
    const float* __restrict__ v,
    const float* __restrict__ wq, const float* __restrict__ wk,
    const float* __restrict__ wv, const float* __restrict__ wo,
    const int* __restrict__ mask)
{
    int blk = blockIdx.x;
    if (blk < PRE_X) {
        int t = blk / XBLK;                      // 0..2
        int bi = blk % XBLK;
        const float* s = (t == 0) ? q : (t == 1) ? k : v;
        size_t e0 = (size_t)(bi * 256 + threadIdx.x) * 4;
        do_convert4(s, g_Xhi + (size_t)t * XN_, g_Xlo + (size_t)t * XN_, e0);
    } else if (blk < PRE_X + PRE_W) {
        int r = blk - PRE_X;
        int t = r / WBLK;                        // 0..3
        int bi = r % WBLK;
        const float* s = (t == 0) ? wq : (t == 1) ? wk : (t == 2) ? wv : wo;
        size_t e0 = (size_t)(bi * 256 + threadIdx.x) * 4;
        do_convert4(s, g_WhiA + (size_t)t * WN_, g_WloA + (size_t)t * WN_, e0);
    } else {
        int w = (blk - PRE_X - PRE_W) * 256 + threadIdx.x;
        const int* src = mask + (size_t)w * 32;
        uint32_t bv = 0;
        #pragma unroll
        for (int i = 0; i < 8; ++i) {
            int4 m4 = *(const int4*)&src[i * 4];
            bv |= (uint32_t)(m4.x & 1) << (4 * i + 0);
            bv |= (uint32_t)(m4.y & 1) << (4 * i + 1);
            bv |= (uint32_t)(m4.z & 1) << (4 * i + 2);
            bv |= (uint32_t)(m4.w & 1) << (4 * i + 3);
        }
        g_mbits[w] = bv;
    }
}

// ---------------------------------------------------------------------------
// bf16-split GEMM (exact R13 config — measured best): 128x128, 512 threads
// (16 warps 4x4, warp tile 32x32), 3-stage cp.async ring, ONE __syncthreads
// per K-tile, per-kstep interleaved ldmatrix.
// ---------------------------------------------------------------------------
#define GM 128
#define GN 128
#define RW 20
#define STW (4 * 128 * RW)                       // words per stage (40KB)
#define G3_SMEM_BYTES (3 * STW * 4)              // 120KB, 3 stages

__global__ __launch_bounds__(512) void gemm_bf16(
    const __nv_bfloat16* __restrict__ XhiB, const __nv_bfloat16* __restrict__ XloB,
    const __nv_bfloat16* __restrict__ WhiB, const __nv_bfloat16* __restrict__ WloB,
    const float* __restrict__ bias0, const float* __restrict__ bias1,
    const float* __restrict__ bias2,
    float* __restrict__ out0, int layout)
{
    extern __shared__ uint32_t sm3[];

    const int z = blockIdx.z;
    const __nv_bfloat16* Ahi = XhiB + (size_t)z * XN_;
    const __nv_bfloat16* Alo = XloB + (size_t)z * XN_;
    const __nv_bfloat16* Whi = WhiB + (size_t)z * WN_;
    const __nv_bfloat16* Wlo = WloB + (size_t)z * WN_;
    const float* bias = (z == 0) ? bias0 : (z == 1) ? bias1 : bias2;

    const int tid  = threadIdx.x;
    const int wid  = tid >> 5;
    const int lane = tid & 31;
    const int wm   = wid >> 2;
    const int wn   = wid & 3;
    const int gid  = lane >> 2;
    const int tig  = lane & 3;
    const int row0 = blockIdx.x * GM;
    const int col0 = blockIdx.y * GN;

    const int sr = tid >> 2;
    const int sq = tid & 3;
    const uint32_t base = smem_u32(sm3);
    const uint32_t stByte = (sr * RW + sq * 4) * 4;

    const __nv_bfloat16* gA0 = Ahi + (size_t)(row0 + sr) * E_ + sq * 8;
    const __nv_bfloat16* gA1 = Alo + (size_t)(row0 + sr) * E_ + sq * 8;
    const __nv_bfloat16* gB0 = Whi + (size_t)(col0 + sr) * E_ + sq * 8;
    const __nv_bfloat16* gB1 = Wlo + (size_t)(col0 + sr) * E_ + sq * 8;

    const uint32_t SUB = 128 * RW * 4;
    const uint32_t STAGE = STW * 4;

    const uint32_t aOff = ((32 * wm + (lane & 15)) * RW + (lane >> 4) * 4) * 4;
    const uint32_t g    = lane >> 3;
    const uint32_t bOff = ((32 * wn + (g >> 1) * 8 + (lane & 7)) * RW + (g & 1) * 4) * 4;

    float acc[2][4][4];
    #pragma unroll
    for (int mt = 0; mt < 2; ++mt)
        #pragma unroll
        for (int nt = 0; nt < 4; ++nt)
            #pragma unroll
            for (int j = 0; j < 4; ++j) acc[mt][nt][j] = 0.f;

    // prologue: stages 0 and 1 in flight
    #pragma unroll
    for (int p = 0; p < 2; ++p) {
        uint32_t d = base + p * STAGE + stByte;
        int go = p * 32;
        cp_async16(d + 0 * SUB, gA0 + go);
        cp_async16(d + 1 * SUB, gA1 + go);
        cp_async16(d + 2 * SUB, gB0 + go);
        cp_async16(d + 3 * SUB, gB1 + go);
        cp_commit();
    }

    const int NKT = E_ / 32;                     // 24
    int stg_idx = 0;
    for (int kt = 0; kt < NKT; ++kt) {
        cp_wait<1>();                            // stage kt resident
        __syncthreads();                         // also proves compute kt-1 done

        if (kt + 2 < NKT) {                      // prefetch kt+2 into (kt+2)%3
            int pst = stg_idx + 2; if (pst >= 3) pst -= 3;
            uint32_t d = base + pst * STAGE + stByte;
            int go = (kt + 2) * 32;
            cp_async16(d + 0 * SUB, gA0 + go);
            cp_async16(d + 1 * SUB, gA1 + go);
            cp_async16(d + 2 * SUB, gB0 + go);
            cp_async16(d + 3 * SUB, gB1 + go);
        }
        cp_commit();                             // keep group count in lockstep

        const uint32_t stg = base + stg_idx * STAGE;
        const uint32_t aHiB = stg;
        const uint32_t aLoB = stg + SUB;
        const uint32_t bHiB = stg + 2 * SUB;
        const uint32_t bLoB = stg + 3 * SUB;

        #pragma unroll
        for (int ks = 0; ks < 2; ++ks) {
            uint32_t ah[2][4], al[2][4], bh[2][4], bl[2][4];
            #pragma unroll
            for (int mt = 0; mt < 2; ++mt) {
                ldmx4(ah[mt], aHiB + aOff + mt * (16 * RW * 4) + ks * 32);
                ldmx4(al[mt], aLoB + aOff + mt * (16 * RW * 4) + ks * 32);
            }
            #pragma unroll
            for (int p = 0; p < 2; ++p) {
                ldmx4(bh[p], bHiB + bOff + p * (16 * RW * 4) + ks * 32);
                ldmx4(bl[p], bLoB + bOff + p * (16 * RW * 4) + ks * 32);
            }
            #pragma unroll
            for (int mt = 0; mt < 2; ++mt)
                #pragma unroll
                for (int nt = 0; nt < 4; ++nt) {
                    const int p = nt >> 1, j = (nt & 1) * 2;
                    mma_bf16(acc[mt][nt], ah[mt], bh[p][j], bh[p][j + 1]);
                    mma_bf16(acc[mt][nt], ah[mt], bl[p][j], bl[p][j + 1]);
                    mma_bf16(acc[mt][nt], al[mt], bh[p][j], bh[p][j + 1]);
                }
        }
        if (++stg_idx == 3) stg_idx = 0;
    }

    // ---- Epilogue
    #pragma unroll
    for (int mt = 0; mt < 2; ++mt) {
        #pragma unroll
        for (int nt = 0; nt < 4; ++nt) {
            int cc = col0 + 32 * wn + 8 * nt + 2 * tig;
            float b0 = bias[cc], b1 = bias[cc + 1];
            #pragma unroll
            for (int half = 0; half < 2; ++half) {
                int rr = row0 + 32 * wm + 16 * mt + gid + 8 * half;
                float ox = acc[mt][nt][2 * half + 0] + b0;
                float oy = acc[mt][nt][2 * half + 1] + b1;
                if (layout == 0) {
                    float2 o = { ox, oy };
                    *(float2*)&out0[(size_t)rr * E_ + cc] = o;
                } else {
                    int b  = rr >> 10;
                    int s  = rr & (S_ - 1);
                    int hh = cc >> 6;
                    int hd = cc & 63;
                    __nv_bfloat16 hx, lx, hy, ly;
                    split_bf16(ox, hx, lx);
                    split_bf16(oy, hy, ly);
                    if (z <= 1) {
                        __nv_bfloat16* Dhi = (z == 0) ? g_Qhi : g_Khi;
                        __nv_bfloat16* Dlo = (z == 0) ? g_Qlo : g_Klo;
                        size_t idx = ((size_t)(b * H_ + hh) * S_ + s) * HD_ + hd;
                        *(uint32_t*)&Dhi[idx] = pack2h(hx, hy);
                        *(uint32_t*)&Dlo[idx] = pack2h(lx, ly);
                    } else {
                        size_t idx = ((size_t)(b * H_ + hh) * HD_ + hd) * S_ + s;
                        g_Vthi[idx]      = hx;
                        g_Vthi[idx + S_] = hy;
                        g_Vtlo[idx]      = lx;
                        g_Vtlo[idx + S_] = ly;
                    }
                }
            }
        }
    }
}

// ---------------------------------------------------------------------------
// Flash attention (unchanged): pre-split bf16 operands, cp.async
// double-buffered KV, ldmatrix fragment loads, 2 CTAs/SM, max-free softmax,
// bitmask masking, deferred l-reduction.
// ---------------------------------------------------------------------------
#define ATK 64
#define AQ  128
#define AW  36
#define QW  (AQ * AW)
#define KVB (ATK * AW)
#define KVSTAGE (4 * KVB)
#define ASM_WORDS (2 * QW + 2 * KVSTAGE)
#define ASM_BYTES (ASM_WORDS * 4)     // 110592 B -> 2 CTAs = 216KB

__global__ __launch_bounds__(256, 2) void attn_mma(
    const __nv_bfloat16* __restrict__ Qhi, const __nv_bfloat16* __restrict__ Qlo,
    const __nv_bfloat16* __restrict__ Khi, const __nv_bfloat16* __restrict__ Klo,
    const __nv_bfloat16* __restrict__ Vthi, const __nv_bfloat16* __restrict__ Vtlo,
    const uint32_t* __restrict__ mbits,
    __nv_bfloat16* __restrict__ xhi, __nv_bfloat16* __restrict__ xlo)
{
    extern __shared__ uint32_t asm_[];
    uint32_t* sQhi = asm_;
    uint32_t* sQlo = sQhi + QW;

    const int tid  = threadIdx.x;
    const int wid  = tid >> 5;
    const int lane = tid & 31;
    const int gid  = lane >> 2;
    const int tig  = lane & 3;
    const int qt   = blockIdx.x;
    const int bh   = blockIdx.y;
    const int b    = bh / H_;
    const int h    = bh % H_;
    const int q0   = qt * AQ;

    const uint32_t base = smem_u32(asm_);
    const float CEXP = 0.18033688011112042f;     // 0.125 * log2(e)

    const __nv_bfloat16* Qh = Qhi + (size_t)bh * S_ * HD_;
    const __nv_bfloat16* Ql = Qlo + (size_t)bh * S_ * HD_;
    const __nv_bfloat16* Kh = Khi + (size_t)bh * S_ * HD_;
    const __nv_bfloat16* Kl = Klo + (size_t)bh * S_ * HD_;
    const __nv_bfloat16* Vh = Vthi + (size_t)bh * HD_ * S_;
    const __nv_bfloat16* Vl = Vtlo + (size_t)bh * HD_ * S_;

    // ---- stage Q (both buffers) + KV tile 0
    #pragma unroll
    for (int i = 0; i < 8; ++i) {
        int c = tid + i * 256;
        int buf = c >> 10;
        int rem = c & 1023;
        int r = rem >> 3, c16 = rem & 7;
        const __nv_bfloat16* src = (buf ? Ql : Qh) + (size_t)(q0 + r) * HD_ + c16 * 8;
        cp_async16(base + buf * (QW * 4) + r * 144 + c16 * 16, src);
    }
    #pragma unroll
    for (int i = 0; i < 8; ++i) {
        int c = tid + i * 256;
        int buf = c >> 9;
        int rem = c & 511;
        int r = rem >> 3, c16 = rem & 7;
        const __nv_bfloat16* src =
            (buf == 0) ? Kh + (size_t)r * HD_ + c16 * 8 :
            (buf == 1) ? Kl + (size_t)r * HD_ + c16 * 8 :
            (buf == 2) ? Vh + (size_t)r * S_ + c16 * 8 :
                         Vl + (size_t)r * S_ + c16 * 8;
        cp_async16(base + (2 * QW + buf * KVB) * 4 + r * 144 + c16 * 16, src);
    }
    cp_commit();
    cp_wait<0>();
    __syncthreads();

    // ---- per-warp Q fragments (persistent)
    uint32_t qh[4][4], ql[4][4];
    {
        const int r0 = wid * 16;
        #pragma unroll
        for (int ks = 0; ks < 4; ++ks) {
            int bidx = (r0 + gid) * AW + 8 * ks + tig;
            qh[ks][0] = sQhi[bidx];
            qh[ks][1] = sQhi[bidx + 8 * AW];
            qh[ks][2] = sQhi[bidx + 4];
            qh[ks][3] = sQhi[bidx + 8 * AW + 4];
            ql[ks][0] = sQlo[bidx];
            ql[ks][1] = sQlo[bidx + 8 * AW];
            ql[ks][2] = sQlo[bidx + 4];
            ql[ks][3] = sQlo[bidx + 8 * AW + 4];
        }
    }

    float Oa[8][4];
    #pragma unroll
    for (int t = 0; t < 8; ++t)
        #pragma unroll
        for (int j = 0; j < 4; ++j) Oa[t][j] = 0.f;
    float l0 = 0.f, l1 = 0.f;

    const int qr0 = q0 + wid * 16 + gid;
    const uint32_t* mb0 = mbits + ((size_t)b * S_ + qr0) * (S_ / 32);
    const uint32_t* mb1 = mb0 + 8 * (S_ / 32);

    const uint32_t g = lane >> 3;
    const uint32_t fOff = (((g >> 1) * 8 + (lane & 7)) * AW + (g & 1) * 4) * 4;

    const int NT = S_ / ATK;                     // 16
    for (int jt = 0; jt < NT; ++jt) {
        if (jt + 1 < NT) {
            int nst = (jt + 1) & 1;
            int ko = (jt + 1) * ATK;
            #pragma unroll
            for (int i = 0; i < 8; ++i) {
                int c = tid + i * 256;
                int buf = c >> 9;
                int rem = c & 511;
                int r = rem >> 3, c16 = rem & 7;
                const __nv_bfloat16* src =
                    (buf == 0) ? Kh + (size_t)(ko + r) * HD_ + c16 * 8 :
                    (buf == 1) ? Kl + (size_t)(ko + r) * HD_ + c16 * 8 :
                    (buf == 2) ? Vh + (size_t)r * S_ + ko + c16 * 8 :
                                 Vl + (size_t)r * S_ + ko + c16 * 8;
                cp_async16(base + (2 * QW + nst * KVSTAGE + buf * KVB) * 4
                           + r * 144 + c16 * 16, src);
            }
            cp_commit();
            cp_wait<1>();
        } else {
            cp_wait<0>();
        }
        uint2 mw0 = *(const uint2*)&mb0[2 * jt];
        uint2 mw1 = *(const uint2*)&mb1[2 * jt];
        __syncthreads();

        const uint32_t kvByte = base + (2 * QW + (jt & 1) * KVSTAGE) * 4;
        const uint32_t kHiB = kvByte;
        const uint32_t kLoB = kvByte + KVB * 4;
        const uint32_t vHiB = kvByte + 2 * KVB * 4;
        const uint32_t vLoB = kvByte + 3 * KVB * 4;

        // ---- S = Q K^T
        float sa[8][4];
        #pragma unroll
        for (int t = 0; t < 8; ++t)
            #pragma unroll
            for (int j = 0; j < 4; ++j) sa[t][j] = 0.f;

        #pragma unroll
        for (int ks = 0; ks < 4; ++ks) {
            #pragma unroll
            for (int tt = 0; tt < 4; ++tt) {
                uint32_t kh4[4], kl4[4];
                uint32_t a = fOff + (16 * tt * AW + 8 * ks) * 4;
                ldmx4(kh4, kHiB + a);
                ldmx4(kl4, kLoB + a);
                mma_bf16(sa[2 * tt],     qh[ks], kh4[0], kh4[1]);
                mma_bf16(sa[2 * tt],     qh[ks], kl4[0], kl4[1]);
                mma_bf16(sa[2 * tt],     ql[ks], kh4[0], kh4[1]);
                mma_bf16(sa[2 * tt + 1], qh[ks], kh4[2], kh4[3]);
                mma_bf16(sa[2 * tt + 1], qh[ks], kl4[2], kl4[3]);
                mma_bf16(sa[2 * tt + 1], ql[ks], kh4[2], kh4[3]);
            }
        }

        // ---- masked exp (max-free)
        #pragma unroll
        for (int t = 0; t < 8; ++t) {
            int bit = 8 * (t & 3) + 2 * tig;
            uint32_t w0 = (t < 4) ? mw0.x : mw0.y;
            uint32_t w1 = (t < 4) ? mw1.x : mw1.y;
            float p0 = ((w0 >> bit) & 1)       ? ex2(sa[t][0] * CEXP) : 0.f;
            float p1 = ((w0 >> (bit + 1)) & 1) ? ex2(sa[t][1] * CEXP) : 0.f;
            float p2 = ((w1 >> bit) & 1)       ? ex2(sa[t][2] * CEXP) : 0.f;
            float p3 = ((w1 >> (bit + 1)) & 1) ? ex2(sa[t][3] * CEXP) : 0.f;
            sa[t][0] = p0; sa[t][1] = p1; sa[t][2] = p2; sa[t][3] = p3;
            l0 += p0 + p1; l1 += p2 + p3;
        }

        // ---- O += P V
        #pragma unroll
        for (int ks = 0; ks < 4; ++ks) {
            const int t0 = 2 * ks, t1 = 2 * ks + 1;
            uint32_t ah[4], al[4];
            ah[0] = pack_bf16(sa[t0][0], sa[t0][1]);
            ah[1] = pack_bf16(sa[t0][2], sa[t0][3]);
            ah[2] = pack_bf16(sa[t1][0], sa[t1][1]);
            ah[3] = pack_bf16(sa[t1][2], sa[t1][3]);
            {
                __nv_bfloat162 h0 = *(__nv_bfloat162*)&ah[0];
                __nv_bfloat162 h1 = *(__nv_bfloat162*)&ah[1];
                __nv_bfloat162 h2 = *(__nv_bfloat162*)&ah[2];
                __nv_bfloat162 h3 = *(__nv_bfloat162*)&ah[3];
                al[0] = pack_bf16(sa[t0][0] - __bfloat162float(h0.x),
                                  sa[t0][1] - __bfloat162float(h0.y));
                al[1] = pack_bf16(sa[t0][2] - __bfloat162float(h1.x),
                                  sa[t0][3] - __bfloat162float(h1.y));
                al[2] = pack_bf16(sa[t1][0] - __bfloat162float(h2.x),
                                  sa[t1][1] - __bfloat162float(h2.y));
                al[3] = pack_bf16(sa[t1][2] - __bfloat162float(h3.x),
                                  sa[t1][3] - __bfloat162float(h3.y));
            }
            #pragma unroll
            for (int nn = 0; nn < 4; ++nn) {
                uint32_t vh4[4], vl4[4];
                uint32_t a = fOff + (16 * nn * AW + 8 * ks) * 4;
                ldmx4(vh4, vHiB + a);
                ldmx4(vl4, vLoB + a);
                mma_bf16(Oa[2 * nn],     ah, vh4[0], vh4[1]);
                mma_bf16(Oa[2 * nn],     ah, vl4[0], vl4[1]);
                mma_bf16(Oa[2 * nn],     al, vh4[0], vh4[1]);
                mma_bf16(Oa[2 * nn + 1], ah, vh4[2], vh4[3]);
                mma_bf16(Oa[2 * nn + 1], ah, vl4[2], vl4[3]);
                mma_bf16(Oa[2 * nn + 1], al, vh4[2], vh4[3]);
            }
        }
        __syncthreads();
    }

    // ---- single deferred l-reduction
    #pragma unroll
    for (int off = 1; off <= 2; off <<= 1) {
        l0 += __shfl_xor_sync(0xffffffffu, l0, off);
        l1 += __shfl_xor_sync(0xffffffffu, l1, off);
    }

    // ---- epilogue: write pre-split bf16 into O-proj A operand
    float inv0 = (l0 > 0.f) ? 1.f / l0 : 0.f;
    float inv1 = (l1 > 0.f) ? 1.f / l1 : 0.f;
    size_t x0 = ((size_t)b * S_ + qr0) * E_ + h * HD_;
    size_t x1 = x0 + 8 * (size_t)E_;
    #pragma unroll
    for (int t = 0; t < 8; ++t) {
        float a0 = Oa[t][0] * inv0, a1 = Oa[t][1] * inv0;
        float b0 = Oa[t][2] * inv1, b1 = Oa[t][3] * inv1;
        __nv_bfloat16 hx, lx, hy, ly;
        split_bf16(a0, hx, lx); split_bf16(a1, hy, ly);
        *(uint32_t*)&xhi[x0 + 8 * t + 2 * tig] = pack2h(hx, hy);
        *(uint32_t*)&xlo[x0 + 8 * t + 2 * tig] = pack2h(lx, ly);
        split_bf16(b0, hx, lx); split_bf16(b1, hy, ly);
        *(uint32_t*)&xhi[x1 + 8 * t + 2 * tig] = pack2h(hx, hy);
        *(uint32_t*)&xlo[x1 + 8 * t + 2 * tig] = pack2h(lx, ly);
    }
}

// ---------------------------------------------------------------------------
// Launch
// ---------------------------------------------------------------------------
extern "C" void kernel_launch(void* const* d_in, const int* in_sizes, int n_in,
                              void* d_out, int out_size)
{
    const float* query = (const float*)d_in[0];
    const float* key_  = (const float*)d_in[1];
    const float* value = (const float*)d_in[2];
    const int*   mask  = (const int*)d_in[3];
    const float* Wq = (const float*)d_in[4];  const float* bq = (const float*)d_in[5];
    const float* Wk = (const float*)d_in[6];  const float* bk = (const float*)d_in[7];
    const float* Wv = (const float*)d_in[8];  const float* bv = (const float*)d_in[9];
    const float* Wo = (const float*)d_in[10]; const float* bo = (const float*)d_in[11];

    __nv_bfloat16 *xhi, *xlo, *whi, *wlo;
    cudaGetSymbolAddress((void**)&xhi, g_Xhi);
    cudaGetSymbolAddress((void**)&xlo, g_Xlo);
    cudaGetSymbolAddress((void**)&whi, g_WhiA);
    cudaGetSymbolAddress((void**)&wlo, g_WloA);

    __nv_bfloat16 *qhi, *qlo, *khi, *klo, *vthi, *vtlo;
    cudaGetSymbolAddress((void**)&qhi,  g_Qhi);
    cudaGetSymbolAddress((void**)&qlo,  g_Qlo);
    cudaGetSymbolAddress((void**)&khi,  g_Khi);
    cudaGetSymbolAddress((void**)&klo,  g_Klo);
    cudaGetSymbolAddress((void**)&vthi, g_Vthi);
    cudaGetSymbolAddress((void**)&vtlo, g_Vtlo);

    uint32_t* mbits;
    cudaGetSymbolAddress((void**)&mbits, g_mbits);

    cudaFuncSetAttribute(gemm_bf16, cudaFuncAttributeMaxDynamicSharedMemorySize,
                         G3_SMEM_BYTES);
    cudaFuncSetAttribute(attn_mma, cudaFuncAttributeMaxDynamicSharedMemorySize,
                         ASM_BYTES);

    // fused prepass: X/W converts + mask pack in one launch
    prepass_fused<<<PRE_TOTAL, 256>>>(query, key_, value, Wq, Wk, Wv, Wo, mask);

    // fused QKV projection -> pre-split bf16 Q/K/Vt
    gemm_bf16<<<dim3(B_ * S_ / GM, E_ / GN, 3), 512, G3_SMEM_BYTES>>>(
        xhi, xlo, whi, wlo, bq, bk, bv, nullptr, 1);

    // attention -> writes split bf16 directly into X slot 0
    attn_mma<<<dim3(S_ / AQ, BH_), 256, ASM_BYTES>>>(
        qhi, qlo, khi, klo, vthi, vtlo, mbits, xhi, xlo);

    // O-projection (reads X slot 0, W slot 3)
    gemm_bf16<<<dim3(B_ * S_ / GM, E_ / GN, 1), 512, G3_SMEM_BYTES>>>(
        xhi, xlo, whi + 3 * (size_t)WN_, wlo + 3 * (size_t)WN_,
        bo, bo, bo, (float*)d_out, 0);
}